// round 2
// baseline (speedup 1.0000x reference)
#include <cuda_runtime.h>

// Problem: argmax over last dim of [16, 512, 32000] fp32 -> [8192] float indices.
// (reference = softmax then argmax; softmax is monotone, so row-argmax suffices.)
// One CTA per row. float4 coalesced streaming reads, warp+block argmax reduce.
// HBM-bound: 1.049 GB read, ~131 us floor at 8 TB/s.

#define N_ROWS   (16 * 512)   // 8192
#define N_COLS   32000
#define N_VEC4   (N_COLS / 4) // 8000
#define THREADS  512
#define N_WARPS  (THREADS / 32)

__device__ __forceinline__ float neg_inf() {
    return __int_as_float(0xFF800000);
}

__global__ __launch_bounds__(THREADS, 2)
void argmax_rows_kernel(const float* __restrict__ in, float* __restrict__ out) {
    const int row = blockIdx.x;
    const float4* __restrict__ rowp =
        reinterpret_cast<const float4*>(in + (size_t)row * N_COLS);

    float best_v = neg_inf();
    int   best_i = 0;

    // Strided streaming pass: 8000 float4 / 512 threads = ~16 iters/thread.
    // Independent LDG.128s -> high MLP, hides DRAM latency.
    for (int i = threadIdx.x; i < N_VEC4; i += THREADS) {
        float4 v = rowp[i];
        int base = i << 2;
        // strict '>' keeps lowest index on ties within this thread's stripe
        if (v.x > best_v) { best_v = v.x; best_i = base;     }
        if (v.y > best_v) { best_v = v.y; best_i = base + 1; }
        if (v.z > best_v) { best_v = v.z; best_i = base + 2; }
        if (v.w > best_v) { best_v = v.w; best_i = base + 3; }
    }

    // Warp reduce (max value, min index on ties)
    #pragma unroll
    for (int off = 16; off > 0; off >>= 1) {
        float ov = __shfl_down_sync(0xFFFFFFFFu, best_v, off);
        int   oi = __shfl_down_sync(0xFFFFFFFFu, best_i, off);
        if (ov > best_v || (ov == best_v && oi < best_i)) {
            best_v = ov; best_i = oi;
        }
    }

    __shared__ float sv[N_WARPS];
    __shared__ int   si[N_WARPS];

    const int wid = threadIdx.x >> 5;
    const int lid = threadIdx.x & 31;
    if (lid == 0) { sv[wid] = best_v; si[wid] = best_i; }
    __syncthreads();

    if (wid == 0) {
        best_v = (lid < N_WARPS) ? sv[lid] : neg_inf();
        best_i = (lid < N_WARPS) ? si[lid] : 0x7FFFFFFF;
        #pragma unroll
        for (int off = 8; off > 0; off >>= 1) {
            float ov = __shfl_down_sync(0xFFFFFFFFu, best_v, off);
            int   oi = __shfl_down_sync(0xFFFFFFFFu, best_i, off);
            if (ov > best_v || (ov == best_v && oi < best_i)) {
                best_v = ov; best_i = oi;
            }
        }
        if (lid == 0) out[row] = (float)best_i;
    }
}

extern "C" void kernel_launch(void* const* d_in, const int* in_sizes, int n_in,
                              void* d_out, int out_size) {
    const float* in  = (const float*)d_in[0];
    float*       out = (float*)d_out;
    argmax_rows_kernel<<<N_ROWS, THREADS>>>(in, out);
}

// round 3
// speedup vs baseline: 1.0691x; 1.0691x over previous
#include <cuda_runtime.h>

// argmax over last dim of [16, 512, 32000] fp32 -> [8192] float indices.
// Persistent CTAs (no wave transitions), 4 independent accumulator chains
// per thread (high MLP, no serial compare dependence), __ldcs streaming.

#define N_ROWS   (16 * 512)   // 8192
#define N_COLS   32000
#define N_VEC4   (N_COLS / 4) // 8000
#define THREADS  512
#define N_WARPS  (THREADS / 32)
#define GRID     296          // 148 SMs x 2 CTAs (persistent)

__device__ __forceinline__ float neg_inf() {
    return __int_as_float(0xFF800000);
}

__device__ __forceinline__ void upd(float v, int i, float& bv, int& bi) {
    if (v > bv) { bv = v; bi = i; }          // strict '>' => lowest index on tie
}

__device__ __forceinline__ void merge(float ov, int oi, float& bv, int& bi) {
    if (ov > bv || (ov == bv && oi < bi)) { bv = ov; bi = oi; }
}

__global__ __launch_bounds__(THREADS, 2)
void argmax_rows_kernel(const float* __restrict__ in, float* __restrict__ out) {
    __shared__ float sv[N_WARPS];
    __shared__ int   si[N_WARPS];

    const int tid = threadIdx.x;
    const int wid = tid >> 5;
    const int lid = tid & 31;

    for (int row = blockIdx.x; row < N_ROWS; row += GRID) {
        const float4* __restrict__ rowp =
            reinterpret_cast<const float4*>(in + (size_t)row * N_COLS);

        // 4 independent accumulator chains -> 4 concurrent LDG.128 per thread,
        // no serial dependence between loads.
        float bv0 = neg_inf(), bv1 = neg_inf(), bv2 = neg_inf(), bv3 = neg_inf();
        int   bi0 = 0, bi1 = 0, bi2 = 0, bi3 = 0;

        int i = tid;
        // main: 3 iterations of 4x512 vec4 cover [0, 6144)
        #pragma unroll
        for (int j = 0; j < 3; j++, i += 4 * THREADS) {
            float4 v0 = __ldcs(rowp + i);
            float4 v1 = __ldcs(rowp + i + THREADS);
            float4 v2 = __ldcs(rowp + i + 2 * THREADS);
            float4 v3 = __ldcs(rowp + i + 3 * THREADS);
            int b0 = i << 2, b1 = (i + THREADS) << 2,
                b2 = (i + 2 * THREADS) << 2, b3 = (i + 3 * THREADS) << 2;
            upd(v0.x, b0,     bv0, bi0); upd(v0.y, b0 + 1, bv0, bi0);
            upd(v0.z, b0 + 2, bv0, bi0); upd(v0.w, b0 + 3, bv0, bi0);
            upd(v1.x, b1,     bv1, bi1); upd(v1.y, b1 + 1, bv1, bi1);
            upd(v1.z, b1 + 2, bv1, bi1); upd(v1.w, b1 + 3, bv1, bi1);
            upd(v2.x, b2,     bv2, bi2); upd(v2.y, b2 + 1, bv2, bi2);
            upd(v2.z, b2 + 2, bv2, bi2); upd(v2.w, b2 + 3, bv2, bi2);
            upd(v3.x, b3,     bv3, bi3); upd(v3.y, b3 + 1, bv3, bi3);
            upd(v3.z, b3 + 2, bv3, bi3); upd(v3.w, b3 + 3, bv3, bi3);
        }
        // tail: [6144, 8000), strided (3-4 iterations, rotate chains for MLP)
        for (int c = 0; i < N_VEC4; i += THREADS, c++) {
            float4 v = __ldcs(rowp + i);
            int b = i << 2;
            float& bv = (c & 1) ? bv1 : bv0;
            int&   bi = (c & 1) ? bi1 : bi0;
            upd(v.x, b, bv, bi); upd(v.y, b + 1, bv, bi);
            upd(v.z, b + 2, bv, bi); upd(v.w, b + 3, bv, bi);
        }

        // merge chains (lower chain index == lower element index on exact tie
        // is NOT guaranteed by chain order, so use full value/index merge)
        merge(bv1, bi1, bv0, bi0);
        merge(bv3, bi3, bv2, bi2);
        merge(bv2, bi2, bv0, bi0);

        // warp reduce
        #pragma unroll
        for (int off = 16; off > 0; off >>= 1) {
            float ov = __shfl_down_sync(0xFFFFFFFFu, bv0, off);
            int   oi = __shfl_down_sync(0xFFFFFFFFu, bi0, off);
            merge(ov, oi, bv0, bi0);
        }

        if (lid == 0) { sv[wid] = bv0; si[wid] = bi0; }
        __syncthreads();

        if (wid == 0) {
            float fv = (lid < N_WARPS) ? sv[lid] : neg_inf();
            int   fi = (lid < N_WARPS) ? si[lid] : 0x7FFFFFFF;
            #pragma unroll
            for (int off = 8; off > 0; off >>= 1) {
                float ov = __shfl_down_sync(0xFFFFFFFFu, fv, off);
                int   oi = __shfl_down_sync(0xFFFFFFFFu, fi, off);
                merge(ov, oi, fv, fi);
            }
            if (lid == 0) out[row] = (float)fi;
        }
        __syncthreads();   // protect sv/si before next row's writes
    }
}

extern "C" void kernel_launch(void* const* d_in, const int* in_sizes, int n_in,
                              void* d_out, int out_size) {
    const float* in  = (const float*)d_in[0];
    float*       out = (float*)d_out;
    argmax_rows_kernel<<<GRID, THREADS>>>(in, out);
}